// round 2
// baseline (speedup 1.0000x reference)
#include <cuda_runtime.h>

// ---------------------------------------------------------------------------
// Generator network:
//   x1 = z @ w_pre^T + b_pre                      [64, 8192]
//   x0 = relu(BN(conv1x1(x1r, w0, b0)))           [64, 256, 1024]
//   q = wq@x0, k = wk@x0, v = wv@x0
//   e = q^T k  -> softmax rows -> ao = gamma*(v @ attn^T) + x0   (fused)
//   x2 = relu(BN(conv1x1(ao, w1, b1)))            [64, 64, 1024]
//   out = conv1x1(x2, w_out, b_out)               [64, 8, 1024]
//
// All GEMM dims are exact multiples of the tiles -> no bounds checks,
// float4 global loads everywhere.
// ---------------------------------------------------------------------------

namespace {
constexpr int BATCH = 64;
constexpr int L     = 1024;   // 32*32
constexpr int CIN   = 8;
constexpr int C0    = 256;
constexpr int CQK   = 32;
constexpr int FCH   = 64;
constexpr float EPS = 1e-5f;
}

// Scratch (static device globals; no runtime allocation allowed)
__device__ float g_x1[BATCH * CIN * L];
__device__ float g_x0[BATCH * C0 * L];
__device__ float g_q [BATCH * CQK * L];
__device__ float g_k [BATCH * CQK * L];
__device__ float g_v [BATCH * C0 * L];
__device__ float g_e [(size_t)BATCH * L * L];      // energy / attn (in place)
__device__ float g_ao[BATCH * C0 * L];
__device__ float g_x2[BATCH * FCH * L];
__device__ float g_part0[C0 * BATCH * 2];
__device__ float g_ms0  [C0 * 2];
__device__ float g_part1[FCH * BATCH * 2];
__device__ float g_ms1  [FCH * 2];

// ---------------------------------------------------------------------------
// Batched SGEMM, exact-tile version: C[m,n] = sum_k A[m,k]*B[k,n] (+epilogue)
// LA: 0 = A[m*lda+k] (contig k);  1 = A[k*lda+m] (contig m)
// LB: 0 = B[k*ldb+n] (contig n);  1 = B[n*ldb+k] (contig k)
// EPI: 0 none, 1 bias per-m, 2 bias per-n, 3 residual: C = gamma*acc + R
// Requires: M%BM==0, N%BN==0, K%BK==0, lda/ldb multiples of 4,
//           16B-aligned base pointers.
// ---------------------------------------------------------------------------
template <int BM, int BN, int BK, int TM, int TN, int LA, int LB, int EPI>
__global__ void gemm_kernel(const float* __restrict__ A,
                            const float* __restrict__ B,
                            float* __restrict__ C,
                            const float* __restrict__ aux,   // bias or residual
                            const float* __restrict__ gamma, // EPI==3 only
                            int M, int N, int K,
                            int lda, int ldb, int ldc,
                            long long sA, long long sB, long long sC)
{
    constexpr int NT = (BM / TM) * (BN / TN);
    __shared__ float As[BK][BM + 4];
    __shared__ float Bs[BK][BN + 4];

    const int tid = threadIdx.x;
    const int bz  = blockIdx.z;
    A += (long long)bz * sA;
    B += (long long)bz * sB;
    C += (long long)bz * sC;

    const int m0 = blockIdx.y * BM;
    const int n0 = blockIdx.x * BN;
    const int tn = tid % (BN / TN);
    const int tm = tid / (BN / TN);

    float acc[TM][TN];
#pragma unroll
    for (int i = 0; i < TM; i++)
#pragma unroll
        for (int j = 0; j < TN; j++) acc[i][j] = 0.f;

    for (int k0 = 0; k0 < K; k0 += BK) {
        // ---- load A tile (float4 global loads) ----
        if (LA == 0) {
            constexpr int CNT = BM * BK / 4;
#pragma unroll
            for (int idx = tid; idx < CNT; idx += NT) {
                int mm = idx / (BK / 4);
                int kq = idx - mm * (BK / 4);
                float4 v4 = *(const float4*)&A[(long long)(m0 + mm) * lda + k0 + kq * 4];
                As[kq * 4 + 0][mm] = v4.x;
                As[kq * 4 + 1][mm] = v4.y;
                As[kq * 4 + 2][mm] = v4.z;
                As[kq * 4 + 3][mm] = v4.w;
            }
        } else {
            constexpr int CNT = BM * BK / 4;
#pragma unroll
            for (int idx = tid; idx < CNT; idx += NT) {
                int kk = idx / (BM / 4);
                int mq = idx - kk * (BM / 4);
                float4 v4 = *(const float4*)&A[(long long)(k0 + kk) * lda + m0 + mq * 4];
                *(float4*)&As[kk][mq * 4] = v4;
            }
        }
        // ---- load B tile ----
        if (LB == 0) {
            constexpr int CNT = BN * BK / 4;
#pragma unroll
            for (int idx = tid; idx < CNT; idx += NT) {
                int kk = idx / (BN / 4);
                int nq = idx - kk * (BN / 4);
                float4 v4 = *(const float4*)&B[(long long)(k0 + kk) * ldb + n0 + nq * 4];
                *(float4*)&Bs[kk][nq * 4] = v4;
            }
        } else {
            constexpr int CNT = BN * BK / 4;
#pragma unroll
            for (int idx = tid; idx < CNT; idx += NT) {
                int nn = idx / (BK / 4);
                int kq = idx - nn * (BK / 4);
                float4 v4 = *(const float4*)&B[(long long)(n0 + nn) * ldb + k0 + kq * 4];
                Bs[kq * 4 + 0][nn] = v4.x;
                Bs[kq * 4 + 1][nn] = v4.y;
                Bs[kq * 4 + 2][nn] = v4.z;
                Bs[kq * 4 + 3][nn] = v4.w;
            }
        }
        __syncthreads();

#pragma unroll
        for (int kk = 0; kk < BK; kk++) {
            float ra[TM], rb[TN];
            if (TM % 4 == 0) {
#pragma unroll
                for (int i = 0; i < TM; i += 4)
                    *(float4*)&ra[i] = *(const float4*)&As[kk][tm * TM + i];
            } else {
#pragma unroll
                for (int i = 0; i < TM; i++) ra[i] = As[kk][tm * TM + i];
            }
            if (TN % 4 == 0) {
#pragma unroll
                for (int j = 0; j < TN; j += 4)
                    *(float4*)&rb[j] = *(const float4*)&Bs[kk][tn * TN + j];
            } else {
#pragma unroll
                for (int j = 0; j < TN; j++) rb[j] = Bs[kk][tn * TN + j];
            }
#pragma unroll
            for (int i = 0; i < TM; i++)
#pragma unroll
                for (int j = 0; j < TN; j++) acc[i][j] += ra[i] * rb[j];
        }
        __syncthreads();
    }

    const float gm = (EPI == 3) ? gamma[0] : 0.f;
#pragma unroll
    for (int i = 0; i < TM; i++) {
        int m = m0 + tm * TM + i;
#pragma unroll
        for (int j = 0; j < TN; j++) {
            int n = n0 + tn * TN + j;
            float v = acc[i][j];
            if (EPI == 1) v += aux[m];
            if (EPI == 2) v += aux[n];
            if (EPI == 3) v = gm * v + aux[(long long)bz * sC + (long long)m * ldc + n];
            C[(long long)m * ldc + n] = v;
        }
    }
}

// ---------------------------------------------------------------------------
// conv0 (8 -> 256): per-pixel form. Each thread owns one (b,l); streams all
// 256 channel outputs with w0 resident in smem. Writes coalesced over l.
// ---------------------------------------------------------------------------
__global__ void conv0_kernel(const float* __restrict__ x1,
                             const float* __restrict__ w0,
                             const float* __restrict__ b0,
                             float* __restrict__ y)
{
    __shared__ float sw[C0 * CIN];   // 8 KB
    __shared__ float sb[C0];
    for (int i = threadIdx.x; i < C0 * CIN; i += 256) sw[i] = w0[i];
    for (int i = threadIdx.x; i < C0; i += 256) sb[i] = b0[i];
    __syncthreads();

    int b = blockIdx.y;
    int l = blockIdx.x * 256 + threadIdx.x;
    float xv[CIN];
#pragma unroll
    for (int c = 0; c < CIN; c++) xv[c] = x1[((size_t)b * CIN + c) * L + l];

    float* yb = y + (size_t)b * C0 * L + l;
#pragma unroll 4
    for (int o = 0; o < C0; o++) {
        float s = sb[o];
#pragma unroll
        for (int c = 0; c < CIN; c++) s = fmaf(sw[o * CIN + c], xv[c], s);
        yb[(size_t)o * L] = s;
    }
}

// ---------------------------------------------------------------------------
// BN stats: per-(channel,batch) partials over L, deterministic fixed-order.
// ---------------------------------------------------------------------------
__global__ void stats_part_kernel(const float* __restrict__ y,
                                  float* __restrict__ part, int C)
{
    int c = blockIdx.x, b = blockIdx.y;
    const float* p = y + ((size_t)b * C + c) * L;
    float s = 0.f, ss = 0.f;
    for (int l = threadIdx.x * 4; l < L; l += blockDim.x * 4) {
        float4 v4 = *(const float4*)&p[l];
        s  += v4.x + v4.y + v4.z + v4.w;
        ss += v4.x * v4.x + v4.y * v4.y + v4.z * v4.z + v4.w * v4.w;
    }
    __shared__ float shs[32], shss[32];
    int lane = threadIdx.x & 31, wid = threadIdx.x >> 5;
#pragma unroll
    for (int o = 16; o > 0; o >>= 1) {
        s  += __shfl_down_sync(0xffffffffu, s, o);
        ss += __shfl_down_sync(0xffffffffu, ss, o);
    }
    if (lane == 0) { shs[wid] = s; shss[wid] = ss; }
    __syncthreads();
    if (wid == 0) {
        int nw = blockDim.x >> 5;
        s  = (lane < nw) ? shs[lane]  : 0.f;
        ss = (lane < nw) ? shss[lane] : 0.f;
#pragma unroll
        for (int o = 16; o > 0; o >>= 1) {
            s  += __shfl_down_sync(0xffffffffu, s, o);
            ss += __shfl_down_sync(0xffffffffu, ss, o);
        }
        if (lane == 0) {
            part[((size_t)c * gridDim.y + b) * 2 + 0] = s;
            part[((size_t)c * gridDim.y + b) * 2 + 1] = ss;
        }
    }
}

__global__ void stats_final_kernel(const float* __restrict__ part,
                                   float* __restrict__ ms, int nb, float invN)
{
    int c = blockIdx.x;
    float s = 0.f, ss = 0.f;
    for (int i = threadIdx.x; i < nb; i += 32) {
        s  += part[((size_t)c * nb + i) * 2 + 0];
        ss += part[((size_t)c * nb + i) * 2 + 1];
    }
#pragma unroll
    for (int o = 16; o > 0; o >>= 1) {
        s  += __shfl_down_sync(0xffffffffu, s, o);
        ss += __shfl_down_sync(0xffffffffu, ss, o);
    }
    if (threadIdx.x == 0) {
        float m   = s * invN;
        float var = ss * invN - m * m;
        ms[c * 2 + 0] = m;
        ms[c * 2 + 1] = rsqrtf(var + EPS);
    }
}

// Vectorized BN+ReLU: one float4 per thread (channel constant within float4).
__global__ void bn_relu_kernel(float* __restrict__ y,
                               const float* __restrict__ ms,
                               const float* __restrict__ g,
                               const float* __restrict__ be,
                               int C, size_t total4)
{
    size_t i = (size_t)blockIdx.x * blockDim.x + threadIdx.x;
    if (i >= total4) return;
    size_t e0 = i * 4;
    int c = (int)((e0 >> 10) % C);
    float mean = ms[c * 2], inv = ms[c * 2 + 1];
    float sc = inv * g[c];
    float sh = be[c] - mean * sc;
    float4 v = *(float4*)&y[e0];
    v.x = fmaxf(fmaf(v.x, sc, sh), 0.f);
    v.y = fmaxf(fmaf(v.y, sc, sh), 0.f);
    v.z = fmaxf(fmaf(v.z, sc, sh), 0.f);
    v.w = fmaxf(fmaf(v.w, sc, sh), 0.f);
    *(float4*)&y[e0] = v;
}

// ---------------------------------------------------------------------------
// Row softmax over rows of length L=1024. 256 threads, 4 values/thread.
// ---------------------------------------------------------------------------
__global__ void softmax_kernel(float* __restrict__ e)
{
    float* row = e + (size_t)blockIdx.x * L;
    int tid = threadIdx.x;
    float4 x = *(float4*)&row[tid * 4];
    float mx = fmaxf(fmaxf(x.x, x.y), fmaxf(x.z, x.w));
    __shared__ float shm[32];
    __shared__ float shsum[32];
    int lane = tid & 31, wid = tid >> 5;
#pragma unroll
    for (int o = 16; o > 0; o >>= 1)
        mx = fmaxf(mx, __shfl_xor_sync(0xffffffffu, mx, o));
    if (lane == 0) shm[wid] = mx;
    __syncthreads();
    mx = shm[0];
#pragma unroll
    for (int w = 1; w < 8; w++) mx = fmaxf(mx, shm[w]);

    x.x = __expf(x.x - mx); x.y = __expf(x.y - mx);
    x.z = __expf(x.z - mx); x.w = __expf(x.w - mx);
    float s = x.x + x.y + x.z + x.w;
#pragma unroll
    for (int o = 16; o > 0; o >>= 1)
        s += __shfl_xor_sync(0xffffffffu, s, o);
    if (lane == 0) shsum[wid] = s;
    __syncthreads();
    s = 0.f;
#pragma unroll
    for (int w = 0; w < 8; w++) s += shsum[w];
    float inv = 1.f / s;
    x.x *= inv; x.y *= inv; x.z *= inv; x.w *= inv;
    *(float4*)&row[tid * 4] = x;
}

// ---------------------------------------------------------------------------
// outconv (64 -> 8): per-pixel, x2 channel strip in registers.
// ---------------------------------------------------------------------------
__global__ void outconv_kernel(const float* __restrict__ x2,
                               const float* __restrict__ wo,
                               const float* __restrict__ bo,
                               float* __restrict__ out)
{
    __shared__ float sw[CIN * FCH];  // 2 KB
    __shared__ float sb[CIN];
    for (int i = threadIdx.x; i < CIN * FCH; i += 256) sw[i] = wo[i];
    if (threadIdx.x < CIN) sb[threadIdx.x] = bo[threadIdx.x];
    __syncthreads();

    int b = blockIdx.y;
    int l = blockIdx.x * 256 + threadIdx.x;
    float xv[FCH];
#pragma unroll
    for (int f = 0; f < FCH; f++) xv[f] = x2[((size_t)b * FCH + f) * L + l];

    float* ob = out + (size_t)b * CIN * L + l;
#pragma unroll
    for (int o = 0; o < CIN; o++) {
        float s = sb[o];
#pragma unroll
        for (int f = 0; f < FCH; f++) s = fmaf(sw[o * FCH + f], xv[f], s);
        ob[(size_t)o * L] = s;
    }
}

// ---------------------------------------------------------------------------
extern "C" void kernel_launch(void* const* d_in, const int* in_sizes, int n_in,
                              void* d_out, int out_size)
{
    const float* z     = (const float*)d_in[0];
    const float* w_pre = (const float*)d_in[1];
    const float* b_pre = (const float*)d_in[2];
    const float* w0    = (const float*)d_in[3];
    const float* b0    = (const float*)d_in[4];
    const float* g0    = (const float*)d_in[5];
    const float* be0   = (const float*)d_in[6];
    const float* wq    = (const float*)d_in[7];
    const float* bq    = (const float*)d_in[8];
    const float* wk    = (const float*)d_in[9];
    const float* bk    = (const float*)d_in[10];
    const float* wv    = (const float*)d_in[11];
    const float* bv    = (const float*)d_in[12];
    const float* gamma = (const float*)d_in[13];
    const float* w1    = (const float*)d_in[14];
    const float* b1    = (const float*)d_in[15];
    const float* g1    = (const float*)d_in[16];
    const float* be1   = (const float*)d_in[17];
    const float* w_out = (const float*)d_in[18];
    const float* b_out = (const float*)d_in[19];
    float* out = (float*)d_out;

    float *x1, *x0, *qb, *kb, *vb, *eb, *ao, *x2, *p0, *ms0, *p1, *ms1;
    cudaGetSymbolAddress((void**)&x1,  g_x1);
    cudaGetSymbolAddress((void**)&x0,  g_x0);
    cudaGetSymbolAddress((void**)&qb,  g_q);
    cudaGetSymbolAddress((void**)&kb,  g_k);
    cudaGetSymbolAddress((void**)&vb,  g_v);
    cudaGetSymbolAddress((void**)&eb,  g_e);
    cudaGetSymbolAddress((void**)&ao,  g_ao);
    cudaGetSymbolAddress((void**)&x2,  g_x2);
    cudaGetSymbolAddress((void**)&p0,  g_part0);
    cudaGetSymbolAddress((void**)&ms0, g_ms0);
    cudaGetSymbolAddress((void**)&p1,  g_part1);
    cudaGetSymbolAddress((void**)&ms1, g_ms1);

    const float invN = 1.f / (float)(BATCH * L);

    // 1. pre-linear: x1[64, 8192] = z[64,128] @ w_pre^T + b_pre   (NT, bias-n)
    gemm_kernel<64, 128, 16, 4, 8, 0, 1, 2><<<dim3(64, 1, 1), 256>>>(
        z, w_pre, x1, b_pre, nullptr, 64, CIN * L, 128, 128, 128, CIN * L,
        0, 0, 0);

    // 2. conv0 (8 -> 256)
    conv0_kernel<<<dim3(L / 256, BATCH), 256>>>(x1, w0, b0, x0);

    // 3. BN0 + relu (in place)
    stats_part_kernel<<<dim3(C0, BATCH), 256>>>(x0, p0, C0);
    stats_final_kernel<<<C0, 32>>>(p0, ms0, BATCH, invN);
    bn_relu_kernel<<<(BATCH * C0 * L / 4 + 255) / 256, 256>>>(
        x0, ms0, g0, be0, C0, (size_t)BATCH * C0 * L / 4);

    // 4. q, k, v projections (batched NN, bias-m)
    gemm_kernel<32, 128, 16, 2, 8, 0, 0, 1><<<dim3(8, 1, BATCH), 256>>>(
        wq, x0, qb, bq, nullptr, CQK, L, C0, C0, L, L, 0, C0 * L, CQK * L);
    gemm_kernel<32, 128, 16, 2, 8, 0, 0, 1><<<dim3(8, 1, BATCH), 256>>>(
        wk, x0, kb, bk, nullptr, CQK, L, C0, C0, L, L, 0, C0 * L, CQK * L);
    gemm_kernel<128, 128, 16, 8, 8, 0, 0, 1><<<dim3(8, 2, BATCH), 256>>>(
        wv, x0, vb, bv, nullptr, C0, L, C0, C0, L, L, 0, C0 * L, C0 * L);

    // 5. energy: e[b,i,j] = sum_c q[b,c,i] k[b,c,j]   (TN)
    gemm_kernel<128, 128, 16, 8, 8, 1, 0, 0><<<dim3(8, 8, BATCH), 256>>>(
        qb, kb, eb, nullptr, nullptr, L, L, CQK, L, L, L,
        CQK * L, CQK * L, (long long)L * L);

    // 6. softmax rows (in place)
    softmax_kernel<<<BATCH * L, 256>>>(eb);

    // 7+8. out fused with residual: ao = gamma*(v @ attn^T) + x0   (NT)
    gemm_kernel<128, 128, 16, 8, 8, 0, 1, 3><<<dim3(8, 2, BATCH), 256>>>(
        vb, eb, ao, x0, gamma, C0, L, L, L, L, L,
        C0 * L, (long long)L * L, C0 * L);

    // 9. conv1 (256 -> 64), batched NN, bias-m
    gemm_kernel<64, 128, 16, 4, 8, 0, 0, 1><<<dim3(8, 1, BATCH), 256>>>(
        w1, ao, x2, b1, nullptr, FCH, L, C0, C0, L, L, 0, C0 * L, FCH * L);

    // 10. BN1 + relu (in place)
    stats_part_kernel<<<dim3(FCH, BATCH), 256>>>(x2, p1, FCH);
    stats_final_kernel<<<FCH, 32>>>(p1, ms1, BATCH, invN);
    bn_relu_kernel<<<(BATCH * FCH * L / 4 + 255) / 256, 256>>>(
        x2, ms1, g1, be1, FCH, (size_t)BATCH * FCH * L / 4);

    // 11. output conv (64 -> 8)
    outconv_kernel<<<dim3(L / 256, BATCH), 256>>>(x2, w_out, b_out, out);
}

// round 5
// speedup vs baseline: 2.1589x; 2.1589x over previous
#include <cuda_runtime.h>
#include <cstdint>

// ---------------------------------------------------------------------------
// Generator network (tf32 tensor-core path):
//   x1 = z @ w_pre^T + b_pre                      [64, 8192]          (fp32)
//   x0 = relu(BN(conv1x1(x1r, w0, b0)))           [64, 256, 1024]     (fp32)
//   qk = wqk@x0  (packed q|k)                     (tf32 mma, BM=64)
//   v  = wv@x0                                    (tf32 mma, BM=128)
//   e = q^T k                                     (tf32 mma, BM=128)
//   softmax rows                                  (fp32)
//   ao = gamma*(v @ attn^T) + x0                  (tf32 mma, fused residual)
//   x2 = relu(BN(conv1x1(ao, w1, b1)))            (tf32 mma, BM=64)
//   out = conv1x1(x2, w_out, b_out)               [64, 8, 1024]       (fp32)
// ---------------------------------------------------------------------------

namespace {
constexpr int BATCH = 64;
constexpr int L     = 1024;   // 32*32
constexpr int CIN   = 8;
constexpr int C0    = 256;
constexpr int CQK   = 32;
constexpr int FCH   = 64;
constexpr float EPS = 1e-5f;
}

// Scratch (static device globals; no runtime allocation allowed)
__device__ float g_x1[BATCH * CIN * L];
__device__ float g_x0[BATCH * C0 * L];
__device__ float g_qk[BATCH * 2 * CQK * L];        // q rows 0..31, k rows 32..63
__device__ float g_v [BATCH * C0 * L];
__device__ float g_e [(size_t)BATCH * L * L];      // energy / attn (in place)
__device__ float g_ao[BATCH * C0 * L];
__device__ float g_x2[BATCH * FCH * L];
__device__ float g_wqk[2 * CQK * C0];
__device__ float g_bqk[2 * CQK];
__device__ float g_part0[C0 * BATCH * 2];
__device__ float g_ms0  [C0 * 2];
__device__ float g_part1[FCH * BATCH * 2];
__device__ float g_ms1  [FCH * 2];

// ---------------------------------------------------------------------------
// tf32 helpers
// ---------------------------------------------------------------------------
__device__ __forceinline__ uint32_t f2tf32(float f) {
    uint32_t r;
    asm("cvt.rna.tf32.f32 %0, %1;" : "=r"(r) : "f"(f));
    return r;
}

__device__ __forceinline__ void mma_tf32(float* c, const uint32_t* a,
                                         const uint32_t* b) {
    asm volatile(
        "mma.sync.aligned.m16n8k8.row.col.f32.tf32.tf32.f32 "
        "{%0,%1,%2,%3}, {%4,%5,%6,%7}, {%8,%9}, {%0,%1,%2,%3};"
        : "+f"(c[0]), "+f"(c[1]), "+f"(c[2]), "+f"(c[3])
        : "r"(a[0]), "r"(a[1]), "r"(a[2]), "r"(a[3]), "r"(b[0]), "r"(b[1]));
}

// ---------------------------------------------------------------------------
// tf32 tensor-core batched GEMM: C[m,n] = sum_k A[m,k]*B[k,n] (+epilogue)
// Fixed tile: BM=BN=128, BK=32, 256 threads (8 warps, warp tile 32x64).
// LA: 0 = A[m*lda+k] (contig k);  1 = A[k*lda+m] (contig m)
// LB: 0 = B[k*ldb+n] (contig n);  1 = B[n*ldb+k] (contig k)
// EPI: 0 none, 1 bias per-m, 3 residual: C = gamma*acc + R (R layout == C)
// Requires M%128==0, N%128==0, K%32==0, 16B-aligned rows.
// Fragment-load bank audit: stride 136 words -> bank (8*cc + gr) % 32,
// all 32 lanes distinct -> conflict-free.
// ---------------------------------------------------------------------------
template <int LA, int LB, int EPI>
__global__ __launch_bounds__(256, 2)
void gemm_tf32_kernel(const float* __restrict__ A,
                      const float* __restrict__ B,
                      float* __restrict__ C,
                      const float* __restrict__ aux,   // bias or residual
                      const float* __restrict__ gamma, // EPI==3 only
                      int K, int lda, int ldb, int ldc,
                      long long sA, long long sB, long long sC)
{
    constexpr int BM = 128, BN = 128, BK = 32;
    constexpr int PAD = 8;
    __shared__ float As[BK][BM + PAD];
    __shared__ float Bs[BK][BN + PAD];

    const int tid  = threadIdx.x;
    const int bz   = blockIdx.z;
    A += (long long)bz * sA;
    B += (long long)bz * sB;
    C += (long long)bz * sC;

    const int m0 = blockIdx.y * BM;
    const int n0 = blockIdx.x * BN;

    const int lane = tid & 31;
    const int warp = tid >> 5;
    const int wm = (warp & 3) * 32;   // 4 warps over M
    const int wn = (warp >> 2) * 64;  // 2 warps over N
    const int gr = lane >> 2;         // 0..7
    const int cc = lane & 3;          // 0..3

    float acc[2][8][4];
#pragma unroll
    for (int i = 0; i < 2; i++)
#pragma unroll
        for (int j = 0; j < 8; j++)
#pragma unroll
            for (int r = 0; r < 4; r++) acc[i][j][r] = 0.f;

    for (int k0 = 0; k0 < K; k0 += BK) {
        // ---- stage A tile into As[k][m] (tf32-converted) ----
        if (LA == 0) {
#pragma unroll
            for (int it = 0; it < 4; it++) {
                int idx = tid + it * 256;
                int q = idx & 7;         // k quad
                int m = idx >> 3;        // 0..127
                float4 v = *(const float4*)&A[(long long)(m0 + m) * lda + k0 + q * 4];
                As[q * 4 + 0][m] = __uint_as_float(f2tf32(v.x));
                As[q * 4 + 1][m] = __uint_as_float(f2tf32(v.y));
                As[q * 4 + 2][m] = __uint_as_float(f2tf32(v.z));
                As[q * 4 + 3][m] = __uint_as_float(f2tf32(v.w));
            }
        } else {
#pragma unroll
            for (int it = 0; it < 4; it++) {
                int idx = tid + it * 256;
                int mq = idx & 31;
                int kk = idx >> 5;
                float4 v = *(const float4*)&A[(long long)(k0 + kk) * lda + m0 + mq * 4];
                v.x = __uint_as_float(f2tf32(v.x));
                v.y = __uint_as_float(f2tf32(v.y));
                v.z = __uint_as_float(f2tf32(v.z));
                v.w = __uint_as_float(f2tf32(v.w));
                *(float4*)&As[kk][mq * 4] = v;
            }
        }
        // ---- stage B tile into Bs[k][n] ----
        if (LB == 0) {
#pragma unroll
            for (int it = 0; it < 4; it++) {
                int idx = tid + it * 256;
                int nq = idx & 31;
                int kk = idx >> 5;
                float4 v = *(const float4*)&B[(long long)(k0 + kk) * ldb + n0 + nq * 4];
                v.x = __uint_as_float(f2tf32(v.x));
                v.y = __uint_as_float(f2tf32(v.y));
                v.z = __uint_as_float(f2tf32(v.z));
                v.w = __uint_as_float(f2tf32(v.w));
                *(float4*)&Bs[kk][nq * 4] = v;
            }
        } else {
#pragma unroll
            for (int it = 0; it < 4; it++) {
                int idx = tid + it * 256;
                int q = idx & 7;
                int n = idx >> 3;
                float4 v = *(const float4*)&B[(long long)(n0 + n) * ldb + k0 + q * 4];
                Bs[q * 4 + 0][n] = __uint_as_float(f2tf32(v.x));
                Bs[q * 4 + 1][n] = __uint_as_float(f2tf32(v.y));
                Bs[q * 4 + 2][n] = __uint_as_float(f2tf32(v.z));
                Bs[q * 4 + 3][n] = __uint_as_float(f2tf32(v.w));
            }
        }
        __syncthreads();

        // ---- compute: 4 k-steps of 8 ----
#pragma unroll
        for (int ks = 0; ks < 4; ks++) {
            const int kb = ks * 8;
            uint32_t a[2][4], b[8][2];
#pragma unroll
            for (int fm = 0; fm < 2; fm++) {
                int m = wm + fm * 16 + gr;
                a[fm][0] = __float_as_uint(As[kb + cc    ][m]);
                a[fm][1] = __float_as_uint(As[kb + cc    ][m + 8]);
                a[fm][2] = __float_as_uint(As[kb + cc + 4][m]);
                a[fm][3] = __float_as_uint(As[kb + cc + 4][m + 8]);
            }
#pragma unroll
            for (int fn = 0; fn < 8; fn++) {
                int n = wn + fn * 8 + gr;
                b[fn][0] = __float_as_uint(Bs[kb + cc    ][n]);
                b[fn][1] = __float_as_uint(Bs[kb + cc + 4][n]);
            }
#pragma unroll
            for (int fm = 0; fm < 2; fm++)
#pragma unroll
                for (int fn = 0; fn < 8; fn++)
                    mma_tf32(acc[fm][fn], a[fm], b[fn]);
        }
        __syncthreads();
    }

    // ---- epilogue ----
    const float gm = (EPI == 3) ? gamma[0] : 0.f;
#pragma unroll
    for (int fm = 0; fm < 2; fm++) {
#pragma unroll
        for (int half = 0; half < 2; half++) {
            int m = m0 + wm + fm * 16 + gr + half * 8;
#pragma unroll
            for (int fn = 0; fn < 8; fn++) {
                int n = n0 + wn + fn * 8 + cc * 2;
                float v0 = acc[fm][fn][half * 2 + 0];
                float v1 = acc[fm][fn][half * 2 + 1];
                if (EPI == 1) { float bb = aux[m]; v0 += bb; v1 += bb; }
                if (EPI == 3) {
                    const float* R = aux + (long long)bz * sC +
                                     (long long)m * ldc + n;
                    v0 = gm * v0 + R[0];
                    v1 = gm * v1 + R[1];
                }
                *(float2*)&C[(long long)m * ldc + n] = make_float2(v0, v1);
            }
        }
    }
}

// ---------------------------------------------------------------------------
// tf32 GEMM, BM=64 variant (A row-major LA=0, B LB=0, bias per-m only).
// 8 warps: 2 over M (32 each), 4 over N (32 each). Warp tile 32x32.
// A-frag bank: stride 72 words -> bank (8*cc + gr + c) % 32, conflict-free.
// Requires M%64==0, N%128==0, K%32==0.
// ---------------------------------------------------------------------------
__global__ __launch_bounds__(256, 2)
void gemm_tf32_64_kernel(const float* __restrict__ A,
                         const float* __restrict__ B,
                         float* __restrict__ C,
                         const float* __restrict__ bias,
                         int K, int lda, int ldb, int ldc,
                         long long sA, long long sB, long long sC)
{
    constexpr int BM = 64, BN = 128, BK = 32;
    constexpr int PAD = 8;
    __shared__ float As[BK][BM + PAD];
    __shared__ float Bs[BK][BN + PAD];

    const int tid  = threadIdx.x;
    const int bz   = blockIdx.z;
    A += (long long)bz * sA;
    B += (long long)bz * sB;
    C += (long long)bz * sC;

    const int m0 = blockIdx.y * BM;
    const int n0 = blockIdx.x * BN;

    const int lane = tid & 31;
    const int warp = tid >> 5;
    const int wm = (warp & 1) * 32;   // 2 warps over M
    const int wn = (warp >> 1) * 32;  // 4 warps over N
    const int gr = lane >> 2;
    const int cc = lane & 3;

    float acc[2][4][4];
#pragma unroll
    for (int i = 0; i < 2; i++)
#pragma unroll
        for (int j = 0; j < 4; j++)
#pragma unroll
            for (int r = 0; r < 4; r++) acc[i][j][r] = 0.f;

    for (int k0 = 0; k0 < K; k0 += BK) {
        // A: 64 m x 8 k-quads = 512 float4 loads, 2 per thread
#pragma unroll
        for (int it = 0; it < 2; it++) {
            int idx = tid + it * 256;
            int q = idx & 7;
            int m = idx >> 3;       // 0..63
            float4 v = *(const float4*)&A[(long long)(m0 + m) * lda + k0 + q * 4];
            As[q * 4 + 0][m] = __uint_as_float(f2tf32(v.x));
            As[q * 4 + 1][m] = __uint_as_float(f2tf32(v.y));
            As[q * 4 + 2][m] = __uint_as_float(f2tf32(v.z));
            As[q * 4 + 3][m] = __uint_as_float(f2tf32(v.w));
        }
        // B: contig n, 32 k x 32 n-quads = 1024 float4 loads, 4 per thread
#pragma unroll
        for (int it = 0; it < 4; it++) {
            int idx = tid + it * 256;
            int nq = idx & 31;
            int kk = idx >> 5;
            float4 v = *(const float4*)&B[(long long)(k0 + kk) * ldb + n0 + nq * 4];
            v.x = __uint_as_float(f2tf32(v.x));
            v.y = __uint_as_float(f2tf32(v.y));
            v.z = __uint_as_float(f2tf32(v.z));
            v.w = __uint_as_float(f2tf32(v.w));
            *(float4*)&Bs[kk][nq * 4] = v;
        }
        __syncthreads();

#pragma unroll
        for (int ks = 0; ks < 4; ks++) {
            const int kb = ks * 8;
            uint32_t a[2][4], b[4][2];
#pragma unroll
            for (int fm = 0; fm < 2; fm++) {
                int m = wm + fm * 16 + gr;
                a[fm][0] = __float_as_uint(As[kb + cc    ][m]);
                a[fm][1] = __float_as_uint(As[kb + cc    ][m + 8]);
                a[fm][2] = __float_as_uint(As[kb + cc + 4][m]);
                a[fm][3] = __float_as_uint(As[kb + cc + 4][m + 8]);
            }
#pragma unroll
            for (int fn = 0; fn < 4; fn++) {
                int n = wn + fn * 8 + gr;
                b[fn][0] = __float_as_uint(Bs[kb + cc    ][n]);
                b[fn][1] = __float_as_uint(Bs[kb + cc + 4][n]);
            }
#pragma unroll
            for (int fm = 0; fm < 2; fm++)
#pragma unroll
                for (int fn = 0; fn < 4; fn++)
                    mma_tf32(acc[fm][fn], a[fm], b[fn]);
        }
        __syncthreads();
    }

#pragma unroll
    for (int fm = 0; fm < 2; fm++) {
#pragma unroll
        for (int half = 0; half < 2; half++) {
            int m = m0 + wm + fm * 16 + gr + half * 8;
            float bb = bias[m];
#pragma unroll
            for (int fn = 0; fn < 4; fn++) {
                int n = n0 + wn + fn * 8 + cc * 2;
                float v0 = acc[fm][fn][half * 2 + 0] + bb;
                float v1 = acc[fm][fn][half * 2 + 1] + bb;
                *(float2*)&C[(long long)m * ldc + n] = make_float2(v0, v1);
            }
        }
    }
}

// ---------------------------------------------------------------------------
// Pack wq||wk and bq||bk (q rows 0..31, k rows 32..63).
// ---------------------------------------------------------------------------
__global__ void concat_qk_kernel(const float* __restrict__ wq,
                                 const float* __restrict__ wk,
                                 const float* __restrict__ bq,
                                 const float* __restrict__ bk,
                                 float* __restrict__ wqk,
                                 float* __restrict__ bqk)
{
    int i = blockIdx.x * 256 + threadIdx.x;    // 64*256 = 16384 total
    if (i < CQK * C0) wqk[i] = wq[i];
    else              wqk[i] = wk[i - CQK * C0];
    if (i < 2 * CQK) bqk[i] = (i < CQK) ? bq[i] : bk[i - CQK];
}

// ---------------------------------------------------------------------------
// fp32 SIMT batched SGEMM (pre-linear only)
// ---------------------------------------------------------------------------
template <int BM, int BN, int BK, int TM, int TN, int LA, int LB, int EPI>
__global__ void gemm_kernel(const float* __restrict__ A,
                            const float* __restrict__ B,
                            float* __restrict__ C,
                            const float* __restrict__ aux,
                            int M, int N, int K,
                            int lda, int ldb, int ldc,
                            long long sA, long long sB, long long sC)
{
    constexpr int NT = (BM / TM) * (BN / TN);
    __shared__ float As[BK][BM + 4];
    __shared__ float Bs[BK][BN + 4];

    const int tid = threadIdx.x;
    const int bz  = blockIdx.z;
    A += (long long)bz * sA;
    B += (long long)bz * sB;
    C += (long long)bz * sC;

    const int m0 = blockIdx.y * BM;
    const int n0 = blockIdx.x * BN;
    const int tn = tid % (BN / TN);
    const int tm = tid / (BN / TN);

    float acc[TM][TN];
#pragma unroll
    for (int i = 0; i < TM; i++)
#pragma unroll
        for (int j = 0; j < TN; j++) acc[i][j] = 0.f;

    for (int k0 = 0; k0 < K; k0 += BK) {
        if (LA == 0) {
            constexpr int CNT = BM * BK / 4;
#pragma unroll
            for (int idx = tid; idx < CNT; idx += NT) {
                int mm = idx / (BK / 4);
                int kq = idx - mm * (BK / 4);
                float4 v4 = *(const float4*)&A[(long long)(m0 + mm) * lda + k0 + kq * 4];
                As[kq * 4 + 0][mm] = v4.x;
                As[kq * 4 + 1][mm] = v4.y;
                As[kq * 4 + 2][mm] = v4.z;
                As[kq * 4 + 3][mm] = v4.w;
            }
        } else {
            constexpr int CNT = BM * BK / 4;
#pragma unroll
            for (int idx = tid; idx < CNT; idx += NT) {
                int kk = idx / (BM / 4);
                int mq = idx - kk * (BM / 4);
                float4 v4 = *(const float4*)&A[(long long)(k0 + kk) * lda + m0 + mq * 4];
                *(float4*)&As[kk][mq * 4] = v4;
            }
        }
        if (LB == 0) {
            constexpr int CNT = BN * BK / 4;
#pragma unroll
            for (int idx = tid; idx < CNT; idx += NT) {
                int kk = idx / (BN / 4);
                int nq = idx - kk * (BN / 4);
                float4 v4 = *(const float4*)&B[(long long)(k0 + kk) * ldb + n0 + nq * 4];
                *(float4*)&Bs[kk][nq * 4] = v4;
            }
        } else {
            constexpr int CNT = BN * BK / 4;
#pragma unroll
            for (int idx = tid; idx < CNT; idx += NT) {
                int nn = idx / (BK / 4);
                int kq = idx - nn * (BK / 4);
                float4 v4 = *(const float4*)&B[(long long)(n0 + nn) * ldb + k0 + kq * 4];
                Bs[kq * 4 + 0][nn] = v4.x;
                Bs[kq * 4 + 1][nn] = v4.y;
                Bs[kq * 4 + 2][nn] = v4.z;
                Bs[kq * 4 + 3][nn] = v4.w;
            }
        }
        __syncthreads();

#pragma unroll
        for (int kk = 0; kk < BK; kk++) {
            float ra[TM], rb[TN];
            if (TM % 4 == 0) {
#pragma unroll
                for (int i = 0; i < TM; i += 4)
                    *(float4*)&ra[i] = *(const float4*)&As[kk][tm * TM + i];
            } else {
#pragma unroll
                for (int i = 0; i < TM; i++) ra[i] = As[kk][tm * TM + i];
            }
#pragma unroll
            for (int j = 0; j < TN; j += 4)
                *(float4*)&rb[j] = *(const float4*)&Bs[kk][tn * TN + j];
#pragma unroll
            for (int i = 0; i < TM; i++)
#pragma unroll
                for (int j = 0; j < TN; j++) acc[i][j] += ra[i] * rb[j];
        }
        __syncthreads();
    }

#pragma unroll
    for (int i = 0; i < TM; i++) {
        int m = m0 + tm * TM + i;
#pragma unroll
        for (int j = 0; j < TN; j++) {
            int n = n0 + tn * TN + j;
            float v = acc[i][j];
            if (EPI == 1) v += aux[m];
            if (EPI == 2) v += aux[n];
            C[(long long)m * ldc + n] = v;
        }
    }
}

// ---------------------------------------------------------------------------
// conv0 (8 -> 256): per-pixel; w0 in smem; coalesced writes.
// ---------------------------------------------------------------------------
__global__ void conv0_kernel(const float* __restrict__ x1,
                             const float* __restrict__ w0,
                             const float* __restrict__ b0,
                             float* __restrict__ y)
{
    __shared__ float sw[C0 * CIN];
    __shared__ float sb[C0];
    for (int i = threadIdx.x; i < C0 * CIN; i += 256) sw[i] = w0[i];
    for (int i = threadIdx.x; i < C0; i += 256) sb[i] = b0[i];
    __syncthreads();

    int b = blockIdx.y;
    int l = blockIdx.x * 256 + threadIdx.x;
    float xv[CIN];
#pragma unroll
    for (int c = 0; c < CIN; c++) xv[c] = x1[((size_t)b * CIN + c) * L + l];

    float* yb = y + (size_t)b * C0 * L + l;
#pragma unroll 4
    for (int o = 0; o < C0; o++) {
        float s = sb[o];
#pragma unroll
        for (int c = 0; c < CIN; c++) s = fmaf(sw[o * CIN + c], xv[c], s);
        yb[(size_t)o * L] = s;
    }
}

// ---------------------------------------------------------------------------
// BN stats (deterministic two-stage)
// ---------------------------------------------------------------------------
__global__ void stats_part_kernel(const float* __restrict__ y,
                                  float* __restrict__ part, int C)
{
    int c = blockIdx.x, b = blockIdx.y;
    const float* p = y + ((size_t)b * C + c) * L;
    float s = 0.f, ss = 0.f;
    for (int l = threadIdx.x * 4; l < L; l += blockDim.x * 4) {
        float4 v4 = *(const float4*)&p[l];
        s  += v4.x + v4.y + v4.z + v4.w;
        ss += v4.x * v4.x + v4.y * v4.y + v4.z * v4.z + v4.w * v4.w;
    }
    __shared__ float shs[32], shss[32];
    int lane = threadIdx.x & 31, wid = threadIdx.x >> 5;
#pragma unroll
    for (int o = 16; o > 0; o >>= 1) {
        s  += __shfl_down_sync(0xffffffffu, s, o);
        ss += __shfl_down_sync(0xffffffffu, ss, o);
    }
    if (lane == 0) { shs[wid] = s; shss[wid] = ss; }
    __syncthreads();
    if (wid == 0) {
        int nw = blockDim.x >> 5;
        s  = (lane < nw) ? shs[lane]  : 0.f;
        ss = (lane < nw) ? shss[lane] : 0.f;
#pragma unroll
        for (int o = 16; o > 0; o >>= 1) {
            s  += __shfl_down_sync(0xffffffffu, s, o);
            ss += __shfl_down_sync(0xffffffffu, ss, o);
        }
        if (lane == 0) {
            part[((size_t)c * gridDim.y + b) * 2 + 0] = s;
            part[((size_t)c * gridDim.y + b) * 2 + 1] = ss;
        }
    }
}

__global__ void stats_final_kernel(const float* __restrict__ part,
                                   float* __restrict__ ms, int nb, float invN)
{
    int c = blockIdx.x;
    float s = 0.f, ss = 0.f;
    for (int i = threadIdx.x; i < nb; i += 32) {
        s  += part[((size_t)c * nb + i) * 2 + 0];
        ss += part[((size_t)c * nb + i) * 2 + 1];
    }
#pragma unroll
    for (int o = 16; o > 0; o >>= 1) {
        s  += __shfl_down_sync(0xffffffffu, s, o);
        ss += __shfl_down_sync(0xffffffffu, ss, o);
    }
    if (threadIdx.x == 0) {
        float m   = s * invN;
        float var = ss * invN - m * m;
        ms[c * 2 + 0] = m;
        ms[c * 2 + 1] = rsqrtf(var + EPS);
    }
}

__global__ void bn_relu_kernel(float* __restrict__ y,
                               const float* __restrict__ ms,
                               const float* __restrict__ g,
                               const float* __restrict__ be,
                               int C, size_t total4)
{
    size_t i = (size_t)blockIdx.x * blockDim.x + threadIdx.x;
    if (i >= total4) return;
    size_t e0 = i * 4;
    int c = (int)((e0 >> 10) % C);
    float mean = ms[c * 2], inv = ms[c * 2 + 1];
    float sc = inv * g[c];
    float sh = be[c] - mean * sc;
    float4 v = *(float4*)&y[e0];
    v.x = fmaxf(fmaf(v.x, sc, sh), 0.f);
    v.y = fmaxf(fmaf(v.y, sc, sh), 0.f);
    v.z = fmaxf(fmaf(v.z, sc, sh), 0.f);
    v.w = fmaxf(fmaf(v.w, sc, sh), 0.f);
    *(float4*)&y[e0] = v;
}

// ---------------------------------------------------------------------------
// Row softmax, L=1024, 256 threads x 4.
// ---------------------------------------------------------------------------
__global__ void softmax_kernel(float* __restrict__ e)
{
    float* row = e + (size_t)blockIdx.x * L;
    int tid = threadIdx.x;
    float4 x = *(float4*)&row[tid * 4];
    float mx = fmaxf(fmaxf(x.x, x.y), fmaxf(x.z, x.w));
    __shared__ float shm[32];
    __shared__ float shsum[32];
    int lane = tid & 31, wid = tid >> 5;
#pragma unroll
    for (int o = 16; o > 0; o >>= 1)
        mx = fmaxf(mx, __shfl_xor_sync(0xffffffffu, mx, o));
    if (lane == 0) shm[wid] = mx;
    __syncthreads();
    mx = shm[0];
#pragma unroll
    for (int w = 1; w < 8; w++) mx = fmaxf(mx, shm[w]);

    x.x = __expf(x.x - mx); x.y = __expf(x.y - mx);
    x.z = __expf(x.z - mx); x.w = __expf(x.w - mx);
    float s = x.x + x.y + x.z + x.w;
#pragma unroll
    for (int o = 16; o > 0; o >>= 1)
        s += __shfl_xor_sync(0xffffffffu, s, o);
    if (lane == 0) shsum[wid] = s;
    __syncthreads();
    s = 0.f;
#pragma unroll
    for (int w = 0; w < 8; w++) s += shsum[w];
    float inv = 1.f / s;
    x.x *= inv; x.y *= inv; x.z *= inv; x.w *= inv;
    *(float4*)&row[tid * 4] = x;
}

// ---------------------------------------------------------------------------
// outconv (64 -> 8)
// ---------------------------------------------------------------------------
__global__ void outconv_kernel(const float* __restrict__ x2,
                               const float* __restrict__ wo,
                               const float* __restrict__ bo,
                               float* __restrict__ out)
{
    __shared__ float sw[CIN * FCH];
    __shared__ float sb[CIN];
    for (int i = threadIdx.x; i < CIN * FCH; i += 256) sw[i] = wo[i];
    if (threadIdx.x < CIN) sb[threadIdx.x] = bo[threadIdx.x];
    __syncthreads();

    int b = blockIdx.y;
    int l = blockIdx.x * 256 + threadIdx.x;
    float xv[FCH];
#pragma unroll
    for (int f = 0; f < FCH; f++) xv[f] = x2[((size_t)b * FCH + f) * L + l];

    float* ob = out + (size_t)b * CIN * L + l;
#pragma unroll
    for (int o = 0; o < CIN; o++) {
        float s = sb[o];
#pragma unroll
        for (int f = 0; f < FCH; f++) s = fmaf(sw[o * FCH + f], xv[f], s);
        ob[(size_t)o * L] = s;
    }
}

// ---------------------------------------------------------------------------
extern "C" void kernel_launch(void* const* d_in, const int* in_sizes, int n_in,
                              void* d_out, int out_size)
{
    const float* z     = (const float*)d_in[0];
    const float* w_pre = (const float*)d_in[1];
    const float* b_pre = (const float*)d_in[2];
    const float* w0    = (const float*)d_in[3];
    const float* b0    = (const float*)d_in[4];
    const float* g0    = (const float*)d_in[5];
    const float* be0   = (const float*)d_in[6];
    const float* wq    = (const float*)d_in[7];
    const float* bq    = (const float*)d_in[8];
    const float* wk    = (const float*)d_in[9];
    const float* bk    = (const float*)d_in[10];
    const float* wv    = (const float*)d_in[11];
    const float* bv    = (const float*)d_in[12];
    const float* gamma = (const float*)d_in[13];
    const float* w1    = (const float*)d_in[14];
    const float* b1    = (const float*)d_in[15];
    const float* g1    = (const float*)d_in[16];
    const float* be1   = (const float*)d_in[17];
    const float* w_out = (const float*)d_in[18];
    const float* b_out = (const float*)d_in[19];
    float* out = (float*)d_out;

    float *x1, *x0, *qk, *vb, *eb, *ao, *x2, *wqk, *bqk;
    float *p0, *ms0, *p1, *ms1;
    cudaGetSymbolAddress((void**)&x1,  g_x1);
    cudaGetSymbolAddress((void**)&x0,  g_x0);
    cudaGetSymbolAddress((void**)&qk,  g_qk);
    cudaGetSymbolAddress((void**)&vb,  g_v);
    cudaGetSymbolAddress((void**)&eb,  g_e);
    cudaGetSymbolAddress((void**)&ao,  g_ao);
    cudaGetSymbolAddress((void**)&x2,  g_x2);
    cudaGetSymbolAddress((void**)&wqk, g_wqk);
    cudaGetSymbolAddress((void**)&bqk, g_bqk);
    cudaGetSymbolAddress((void**)&p0,  g_part0);
    cudaGetSymbolAddress((void**)&ms0, g_ms0);
    cudaGetSymbolAddress((void**)&p1,  g_part1);
    cudaGetSymbolAddress((void**)&ms1, g_ms1);

    const float invN = 1.f / (float)(BATCH * L);

    // 0. pack wq||wk, bq||bk (independent of everything else)
    concat_qk_kernel<<<64, 256>>>(wq, wk, bq, bk, wqk, bqk);

    // 1. pre-linear: x1[64, 8192] = z[64,128] @ w_pre^T + b_pre  (fp32 NT)
    gemm_kernel<64, 128, 16, 4, 8, 0, 1, 2><<<dim3(64, 1, 1), 256>>>(
        z, w_pre, x1, b_pre, 64, CIN * L, 128, 128, 128, CIN * L, 0, 0, 0);

    // 2. conv0 (8 -> 256)
    conv0_kernel<<<dim3(L / 256, BATCH), 256>>>(x1, w0, b0, x0);

    // 3. BN0 + relu (in place)
    stats_part_kernel<<<dim3(C0, BATCH), 256>>>(x0, p0, C0);
    stats_final_kernel<<<C0, 32>>>(p0, ms0, BATCH, invN);
    bn_relu_kernel<<<(BATCH * C0 * L / 4 + 255) / 256, 256>>>(
        x0, ms0, g0, be0, C0, (size_t)BATCH * C0 * L / 4);

    // 4a. packed q|k projection (tf32, BM=64): qk[b,64,L]
    gemm_tf32_64_kernel<<<dim3(8, 1, BATCH), 256>>>(
        wqk, x0, qk, bqk, C0, C0, L, L, 0, C0 * L, 2 * CQK * L);

    // 4b. v projection (tf32, BM=128): A=wv[256,256], bias per-m
    gemm_tf32_kernel<0, 0, 1><<<dim3(8, 2, BATCH), 256>>>(
        wv, x0, vb, bv, nullptr, C0, C0, L, L, 0, C0 * L, C0 * L);

    // 5. energy (tf32): e[b,i,j] = sum_c q[b,c,i] k[b,c,j]
    //    q = qk rows 0..31, k = qk rows 32..63
    gemm_tf32_kernel<1, 0, 0><<<dim3(8, 8, BATCH), 256>>>(
        qk, qk + (size_t)CQK * L, eb, nullptr, nullptr, CQK, L, L, L,
        2 * CQK * L, 2 * CQK * L, (long long)L * L);

    // 6. softmax rows (in place)
    softmax_kernel<<<BATCH * L, 256>>>(eb);

    // 7+8. out GEMM fused residual (tf32): ao = gamma*(v@attn^T) + x0 (NT)
    gemm_tf32_kernel<0, 1, 3><<<dim3(8, 2, BATCH), 256>>>(
        vb, eb, ao, x0, gamma, L, L, L, L,
        C0 * L, (long long)L * L, C0 * L);

    // 9. conv1 (256 -> 64) (tf32, BM=64), bias per-m
    gemm_tf32_64_kernel<<<dim3(8, 1, BATCH), 256>>>(
        w1, ao, x2, b1, C0, C0, L, L, 0, C0 * L, FCH * L);

    // 10. BN1 + relu (in place)
    stats_part_kernel<<<dim3(FCH, BATCH), 256>>>(x2, p1, FCH);
    stats_final_kernel<<<FCH, 32>>>(p1, ms1, BATCH, invN);
    bn_relu_kernel<<<(BATCH * FCH * L / 4 + 255) / 256, 256>>>(
        x2, ms1, g1, be1, FCH, (size_t)BATCH * FCH * L / 4);

    // 11. output conv (64 -> 8)
    outconv_kernel<<<dim3(L / 256, BATCH), 256>>>(x2, w_out, b_out, out);
}

// round 8
// speedup vs baseline: 2.7553x; 1.2763x over previous
#include <cuda_runtime.h>
#include <cstdint>

// ---------------------------------------------------------------------------
// Generator network (tf32 tensor-core path, cp.async 2-stage pipelined GEMMs):
//   x1 = z @ w_pre^T + b_pre                      (fp32)
//   x0 = relu(BN(conv1x1(x1r, w0, b0)))           (fp32)
//   qk = wqk@x0  (packed q|k)                     (tf32, BM=64)
//   v  = wv@x0                                    (tf32, BM=128)
//   e = q^T k                                     (tf32, BM=128)
//   softmax rows                                  (fp32)
//   ao = gamma*(v @ attn^T) + x0                  (tf32, fused residual)
//   x2 = relu(BN(conv1x1(ao, w1, b1)))            (tf32, BM=64)
//   out = conv1x1(x2, w_out, b_out)               (fp32)
// ---------------------------------------------------------------------------

namespace {
constexpr int BATCH = 64;
constexpr int L     = 1024;
constexpr int CIN   = 8;
constexpr int C0    = 256;
constexpr int CQK   = 32;
constexpr int FCH   = 64;
constexpr float EPS = 1e-5f;
}

// Scratch (static device globals; no runtime allocation allowed)
__device__ float g_x1[BATCH * CIN * L];
__device__ float g_x0[BATCH * C0 * L];
__device__ float g_qk[BATCH * 2 * CQK * L];        // q rows 0..31, k rows 32..63
__device__ float g_v [BATCH * C0 * L];
__device__ float g_e [(size_t)BATCH * L * L];      // energy / attn (in place)
__device__ float g_ao[BATCH * C0 * L];
__device__ float g_x2[BATCH * FCH * L];
__device__ float g_wqk[2 * CQK * C0];
__device__ float g_bqk[2 * CQK];
__device__ float g_part0[C0 * BATCH * 2];
__device__ float g_ms0  [C0 * 2];
__device__ float g_part1[FCH * BATCH * 2];
__device__ float g_ms1  [FCH * 2];

// ---------------------------------------------------------------------------
// helpers
// ---------------------------------------------------------------------------
__device__ __forceinline__ uint32_t f2tf32(float f) {
    uint32_t r;
    asm("cvt.rna.tf32.f32 %0, %1;" : "=r"(r) : "f"(f));
    return r;
}

__device__ __forceinline__ void mma_tf32(float* c, const uint32_t* a,
                                         const uint32_t* b) {
    asm volatile(
        "mma.sync.aligned.m16n8k8.row.col.f32.tf32.tf32.f32 "
        "{%0,%1,%2,%3}, {%4,%5,%6,%7}, {%8,%9}, {%0,%1,%2,%3};"
        : "+f"(c[0]), "+f"(c[1]), "+f"(c[2]), "+f"(c[3])
        : "r"(a[0]), "r"(a[1]), "r"(a[2]), "r"(a[3]), "r"(b[0]), "r"(b[1]));
}

__device__ __forceinline__ void cp_async16(const float* smem_dst,
                                           const float* gsrc) {
    uint32_t sa = (uint32_t)__cvta_generic_to_shared(smem_dst);
    asm volatile("cp.async.cg.shared.global [%0], [%1], 16;\n"
                 :: "r"(sa), "l"(gsrc));
}
__device__ __forceinline__ void cp_commit() {
    asm volatile("cp.async.commit_group;\n");
}
__device__ __forceinline__ void cp_wait1() {
    asm volatile("cp.async.wait_group 1;\n");
}

// Smem layout strides (words):
//   contig-k operand  -> row-major [rows][36]   (BK=32 + pad 4)
//   contig-m/n operand-> [BK][136]              (dim 128 + pad 8)
// Fragment bank audit:
//   stride 36 : bank (4*gr + cc) % 32  -> 32 distinct lanes, conflict-free
//   stride 136: bank (8*cc + gr) % 32  -> 32 distinct lanes, conflict-free

// ---------------------------------------------------------------------------
// tf32 pipelined GEMM, BM=BN=128, BK=32, 256 threads (8 warps, 32x64 warp tile)
// LA: 0 = A[m*lda+k] (contig k);  1 = A[k*lda+m] (contig m)
// LB: 0 = B[k*ldb+n] (contig n);  1 = B[n*ldb+k] (contig k)
// EPI: 0 none, 1 bias per-m, 3 residual: C = gamma*acc + R (R layout == C)
// Dynamic smem: 2 stages x (A 4608 + B 4608 words) = 73728 bytes.
// ---------------------------------------------------------------------------
template <int LA, int LB, int EPI>
__global__ __launch_bounds__(256, 2)
void gemm_tf32_kernel(const float* __restrict__ A,
                      const float* __restrict__ B,
                      float* __restrict__ C,
                      const float* __restrict__ aux,
                      const float* __restrict__ gamma,
                      int K, int lda, int ldb, int ldc,
                      long long sA, long long sB, long long sC)
{
    constexpr int BK = 32;
    constexpr int SAW = 4608;
    constexpr int SBW = 4608;
    extern __shared__ float dsm[];
    float* Abuf[2] = {dsm, dsm + SAW};
    float* Bbuf[2] = {dsm + 2 * SAW, dsm + 2 * SAW + SBW};

    const int tid  = threadIdx.x;
    const int bz   = blockIdx.z;
    A += (long long)bz * sA;
    B += (long long)bz * sB;
    C += (long long)bz * sC;

    const int m0 = blockIdx.y * 128;
    const int n0 = blockIdx.x * 128;

    const int lane = tid & 31;
    const int warp = tid >> 5;
    const int wm = (warp & 3) * 32;
    const int wn = (warp >> 2) * 64;
    const int gr = lane >> 2;
    const int cc = lane & 3;

    float acc[2][8][4];
#pragma unroll
    for (int i = 0; i < 2; i++)
#pragma unroll
        for (int j = 0; j < 8; j++)
#pragma unroll
            for (int r = 0; r < 4; r++) acc[i][j][r] = 0.f;

    auto load_stage = [&](float* As, float* Bs, int k0) {
        if (LA == 0) {
#pragma unroll
            for (int it = 0; it < 4; it++) {
                int idx = tid + it * 256;
                int q = idx & 7, m = idx >> 3;
                cp_async16(As + m * 36 + q * 4,
                           &A[(long long)(m0 + m) * lda + k0 + q * 4]);
            }
        } else {
#pragma unroll
            for (int it = 0; it < 4; it++) {
                int idx = tid + it * 256;
                int mq = idx & 31, kk = idx >> 5;
                cp_async16(As + kk * 136 + mq * 4,
                           &A[(long long)(k0 + kk) * lda + m0 + mq * 4]);
            }
        }
        if (LB == 0) {
#pragma unroll
            for (int it = 0; it < 4; it++) {
                int idx = tid + it * 256;
                int nq = idx & 31, kk = idx >> 5;
                cp_async16(Bs + kk * 136 + nq * 4,
                           &B[(long long)(k0 + kk) * ldb + n0 + nq * 4]);
            }
        } else {
#pragma unroll
            for (int it = 0; it < 4; it++) {
                int idx = tid + it * 256;
                int q = idx & 7, n = idx >> 3;
                cp_async16(Bs + n * 36 + q * 4,
                           &B[(long long)(n0 + n) * ldb + k0 + q * 4]);
            }
        }
    };

    load_stage(Abuf[0], Bbuf[0], 0);
    cp_commit();
    int cur = 0;

    for (int k0 = 0; k0 < K; k0 += BK) {
        if (k0 + BK < K) load_stage(Abuf[1 - cur], Bbuf[1 - cur], k0 + BK);
        cp_commit();
        cp_wait1();
        __syncthreads();

        const float* As = Abuf[cur];
        const float* Bs = Bbuf[cur];
#pragma unroll
        for (int ks = 0; ks < 4; ks++) {
            const int kb = ks * 8;
            uint32_t a[2][4], b[8][2];
#pragma unroll
            for (int fm = 0; fm < 2; fm++) {
                int m = wm + fm * 16 + gr;
                if (LA == 0) {
                    a[fm][0] = f2tf32(As[m * 36 + kb + cc]);
                    a[fm][1] = f2tf32(As[(m + 8) * 36 + kb + cc]);
                    a[fm][2] = f2tf32(As[m * 36 + kb + cc + 4]);
                    a[fm][3] = f2tf32(As[(m + 8) * 36 + kb + cc + 4]);
                } else {
                    a[fm][0] = f2tf32(As[(kb + cc) * 136 + m]);
                    a[fm][1] = f2tf32(As[(kb + cc) * 136 + m + 8]);
                    a[fm][2] = f2tf32(As[(kb + cc + 4) * 136 + m]);
                    a[fm][3] = f2tf32(As[(kb + cc + 4) * 136 + m + 8]);
                }
            }
#pragma unroll
            for (int fn = 0; fn < 8; fn++) {
                int n = wn + fn * 8 + gr;
                if (LB == 0) {
                    b[fn][0] = f2tf32(Bs[(kb + cc) * 136 + n]);
                    b[fn][1] = f2tf32(Bs[(kb + cc + 4) * 136 + n]);
                } else {
                    b[fn][0] = f2tf32(Bs[n * 36 + kb + cc]);
                    b[fn][1] = f2tf32(Bs[n * 36 + kb + cc + 4]);
                }
            }
#pragma unroll
            for (int fm = 0; fm < 2; fm++)
#pragma unroll
                for (int fn = 0; fn < 8; fn++)
                    mma_tf32(acc[fm][fn], a[fm], b[fn]);
        }
        __syncthreads();
        cur ^= 1;
    }

    const float gm = (EPI == 3) ? gamma[0] : 0.f;
#pragma unroll
    for (int fm = 0; fm < 2; fm++) {
#pragma unroll
        for (int half = 0; half < 2; half++) {
            int m = m0 + wm + fm * 16 + gr + half * 8;
#pragma unroll
            for (int fn = 0; fn < 8; fn++) {
                int n = n0 + wn + fn * 8 + cc * 2;
                float v0 = acc[fm][fn][half * 2 + 0];
                float v1 = acc[fm][fn][half * 2 + 1];
                if (EPI == 1) { float bb = aux[m]; v0 += bb; v1 += bb; }
                if (EPI == 3) {
                    const float* R = aux + (long long)bz * sC +
                                     (long long)m * ldc + n;
                    v0 = gm * v0 + R[0];
                    v1 = gm * v1 + R[1];
                }
                *(float2*)&C[(long long)m * ldc + n] = make_float2(v0, v1);
            }
        }
    }
}

// ---------------------------------------------------------------------------
// tf32 pipelined GEMM, BM=64 (LA=0, LB=0, bias per-m). Warp tile 32x32.
// Dynamic smem: 2 x (2304 + 4608) words = 55296 bytes.
// ---------------------------------------------------------------------------
__global__ __launch_bounds__(256, 2)
void gemm_tf32_64_kernel(const float* __restrict__ A,
                         const float* __restrict__ B,
                         float* __restrict__ C,
                         const float* __restrict__ bias,
                         int K, int lda, int ldb, int ldc,
                         long long sA, long long sB, long long sC)
{
    constexpr int BK = 32;
    constexpr int SAW = 2304;
    constexpr int SBW = 4608;
    extern __shared__ float dsm[];
    float* Abuf[2] = {dsm, dsm + SAW};
    float* Bbuf[2] = {dsm + 2 * SAW, dsm + 2 * SAW + SBW};

    const int tid  = threadIdx.x;
    const int bz   = blockIdx.z;
    A += (long long)bz * sA;
    B += (long long)bz * sB;
    C += (long long)bz * sC;

    const int m0 = blockIdx.y * 64;
    const int n0 = blockIdx.x * 128;

    const int lane = tid & 31;
    const int warp = tid >> 5;
    const int wm = (warp & 1) * 32;
    const int wn = (warp >> 1) * 32;
    const int gr = lane >> 2;
    const int cc = lane & 3;

    float acc[2][4][4];
#pragma unroll
    for (int i = 0; i < 2; i++)
#pragma unroll
        for (int j = 0; j < 4; j++)
#pragma unroll
            for (int r = 0; r < 4; r++) acc[i][j][r] = 0.f;

    auto load_stage = [&](float* As, float* Bs, int k0) {
#pragma unroll
        for (int it = 0; it < 2; it++) {
            int idx = tid + it * 256;
            int q = idx & 7, m = idx >> 3;
            cp_async16(As + m * 36 + q * 4,
                       &A[(long long)(m0 + m) * lda + k0 + q * 4]);
        }
#pragma unroll
        for (int it = 0; it < 4; it++) {
            int idx = tid + it * 256;
            int nq = idx & 31, kk = idx >> 5;
            cp_async16(Bs + kk * 136 + nq * 4,
                       &B[(long long)(k0 + kk) * ldb + n0 + nq * 4]);
        }
    };

    load_stage(Abuf[0], Bbuf[0], 0);
    cp_commit();
    int cur = 0;

    for (int k0 = 0; k0 < K; k0 += BK) {
        if (k0 + BK < K) load_stage(Abuf[1 - cur], Bbuf[1 - cur], k0 + BK);
        cp_commit();
        cp_wait1();
        __syncthreads();

        const float* As = Abuf[cur];
        const float* Bs = Bbuf[cur];
#pragma unroll
        for (int ks = 0; ks < 4; ks++) {
            const int kb = ks * 8;
            uint32_t a[2][4], b[4][2];
#pragma unroll
            for (int fm = 0; fm < 2; fm++) {
                int m = wm + fm * 16 + gr;
                a[fm][0] = f2tf32(As[m * 36 + kb + cc]);
                a[fm][1] = f2tf32(As[(m + 8) * 36 + kb + cc]);
                a[fm][2] = f2tf32(As[m * 36 + kb + cc + 4]);
                a[fm][3] = f2tf32(As[(m + 8) * 36 + kb + cc + 4]);
            }
#pragma unroll
            for (int fn = 0; fn < 4; fn++) {
                int n = wn + fn * 8 + gr;
                b[fn][0] = f2tf32(Bs[(kb + cc) * 136 + n]);
                b[fn][1] = f2tf32(Bs[(kb + cc + 4) * 136 + n]);
            }
#pragma unroll
            for (int fm = 0; fm < 2; fm++)
#pragma unroll
                for (int fn = 0; fn < 4; fn++)
                    mma_tf32(acc[fm][fn], a[fm], b[fn]);
        }
        __syncthreads();
        cur ^= 1;
    }

#pragma unroll
    for (int fm = 0; fm < 2; fm++) {
#pragma unroll
        for (int half = 0; half < 2; half++) {
            int m = m0 + wm + fm * 16 + gr + half * 8;
            float bb = bias[m];
#pragma unroll
            for (int fn = 0; fn < 4; fn++) {
                int n = n0 + wn + fn * 8 + cc * 2;
                float v0 = acc[fm][fn][half * 2 + 0] + bb;
                float v1 = acc[fm][fn][half * 2 + 1] + bb;
                *(float2*)&C[(long long)m * ldc + n] = make_float2(v0, v1);
            }
        }
    }
}

// ---------------------------------------------------------------------------
// Pack wq||wk and bq||bk.
// ---------------------------------------------------------------------------
__global__ void concat_qk_kernel(const float* __restrict__ wq,
                                 const float* __restrict__ wk,
                                 const float* __restrict__ bq,
                                 const float* __restrict__ bk,
                                 float* __restrict__ wqk,
                                 float* __restrict__ bqk)
{
    int i = blockIdx.x * 256 + threadIdx.x;
    if (i < CQK * C0) wqk[i] = wq[i];
    else              wqk[i] = wk[i - CQK * C0];
    if (i < 2 * CQK) bqk[i] = (i < CQK) ? bq[i] : bk[i - CQK];
}

// ---------------------------------------------------------------------------
// fp32 SIMT batched SGEMM (pre-linear only)
// ---------------------------------------------------------------------------
template <int BM, int BN, int BK, int TM, int TN, int LA, int LB, int EPI>
__global__ void gemm_kernel(const float* __restrict__ A,
                            const float* __restrict__ B,
                            float* __restrict__ C,
                            const float* __restrict__ aux,
                            int M, int N, int K,
                            int lda, int ldb, int ldc,
                            long long sA, long long sB, long long sC)
{
    constexpr int NT = (BM / TM) * (BN / TN);
    __shared__ float As[BK][BM + 4];
    __shared__ float Bs[BK][BN + 4];

    const int tid = threadIdx.x;
    const int bz  = blockIdx.z;
    A += (long long)bz * sA;
    B += (long long)bz * sB;
    C += (long long)bz * sC;

    const int m0 = blockIdx.y * BM;
    const int n0 = blockIdx.x * BN;
    const int tn = tid % (BN / TN);
    const int tm = tid / (BN / TN);

    float acc[TM][TN];
#pragma unroll
    for (int i = 0; i < TM; i++)
#pragma unroll
        for (int j = 0; j < TN; j++) acc[i][j] = 0.f;

    for (int k0 = 0; k0 < K; k0 += BK) {
        if (LA == 0) {
            constexpr int CNT = BM * BK / 4;
#pragma unroll
            for (int idx = tid; idx < CNT; idx += NT) {
                int mm = idx / (BK / 4);
                int kq = idx - mm * (BK / 4);
                float4 v4 = *(const float4*)&A[(long long)(m0 + mm) * lda + k0 + kq * 4];
                As[kq * 4 + 0][mm] = v4.x;
                As[kq * 4 + 1][mm] = v4.y;
                As[kq * 4 + 2][mm] = v4.z;
                As[kq * 4 + 3][mm] = v4.w;
            }
        } else {
            constexpr int CNT = BM * BK / 4;
#pragma unroll
            for (int idx = tid; idx < CNT; idx += NT) {
                int kk = idx / (BM / 4);
                int mq = idx - kk * (BM / 4);
                float4 v4 = *(const float4*)&A[(long long)(k0 + kk) * lda + m0 + mq * 4];
                *(float4*)&As[kk][mq * 4] = v4;
            }
        }
        if (LB == 0) {
            constexpr int CNT = BN * BK / 4;
#pragma unroll
            for (int idx = tid; idx < CNT; idx += NT) {
                int kk = idx / (BN / 4);
                int nq = idx - kk * (BN / 4);
                float4 v4 = *(const float4*)&B[(long long)(k0 + kk) * ldb + n0 + nq * 4];
                *(float4*)&Bs[kk][nq * 4] = v4;
            }
        } else {
            constexpr int CNT = BN * BK / 4;
#pragma unroll
            for (int idx = tid; idx < CNT; idx += NT) {
                int nn = idx / (BK / 4);
                int kq = idx - nn * (BK / 4);
                float4 v4 = *(const float4*)&B[(long long)(n0 + nn) * ldb + k0 + kq * 4];
                Bs[kq * 4 + 0][nn] = v4.x;
                Bs[kq * 4 + 1][nn] = v4.y;
                Bs[kq * 4 + 2][nn] = v4.z;
                Bs[kq * 4 + 3][nn] = v4.w;
            }
        }
        __syncthreads();

#pragma unroll
        for (int kk = 0; kk < BK; kk++) {
            float ra[TM], rb[TN];
            if (TM % 4 == 0) {
#pragma unroll
                for (int i = 0; i < TM; i += 4)
                    *(float4*)&ra[i] = *(const float4*)&As[kk][tm * TM + i];
            } else {
#pragma unroll
                for (int i = 0; i < TM; i++) ra[i] = As[kk][tm * TM + i];
            }
#pragma unroll
            for (int j = 0; j < TN; j += 4)
                *(float4*)&rb[j] = *(const float4*)&Bs[kk][tn * TN + j];
#pragma unroll
            for (int i = 0; i < TM; i++)
#pragma unroll
                for (int j = 0; j < TN; j++) acc[i][j] += ra[i] * rb[j];
        }
        __syncthreads();
    }

#pragma unroll
    for (int i = 0; i < TM; i++) {
        int m = m0 + tm * TM + i;
#pragma unroll
        for (int j = 0; j < TN; j++) {
            int n = n0 + tn * TN + j;
            float v = acc[i][j];
            if (EPI == 1) v += aux[m];
            if (EPI == 2) v += aux[n];
            C[(long long)m * ldc + n] = v;
        }
    }
}

// ---------------------------------------------------------------------------
// conv0 (8 -> 256)
// ---------------------------------------------------------------------------
__global__ void conv0_kernel(const float* __restrict__ x1,
                             const float* __restrict__ w0,
                             const float* __restrict__ b0,
                             float* __restrict__ y)
{
    __shared__ float sw[C0 * CIN];
    __shared__ float sb[C0];
    for (int i = threadIdx.x; i < C0 * CIN; i += 256) sw[i] = w0[i];
    for (int i = threadIdx.x; i < C0; i += 256) sb[i] = b0[i];
    __syncthreads();

    int b = blockIdx.y;
    int l = blockIdx.x * 256 + threadIdx.x;
    float xv[CIN];
#pragma unroll
    for (int c = 0; c < CIN; c++) xv[c] = x1[((size_t)b * CIN + c) * L + l];

    float* yb = y + (size_t)b * C0 * L + l;
#pragma unroll 4
    for (int o = 0; o < C0; o++) {
        float s = sb[o];
#pragma unroll
        for (int c = 0; c < CIN; c++) s = fmaf(sw[o * CIN + c], xv[c], s);
        yb[(size_t)o * L] = s;
    }
}

// ---------------------------------------------------------------------------
// BN stats (deterministic two-stage)
// ---------------------------------------------------------------------------
__global__ void stats_part_kernel(const float* __restrict__ y,
                                  float* __restrict__ part, int C)
{
    int c = blockIdx.x, b = blockIdx.y;
    const float* p = y + ((size_t)b * C + c) * L;
    float s = 0.f, ss = 0.f;
    for (int l = threadIdx.x * 4; l < L; l += blockDim.x * 4) {
        float4 v4 = *(const float4*)&p[l];
        s  += v4.x + v4.y + v4.z + v4.w;
        ss += v4.x * v4.x + v4.y * v4.y + v4.z * v4.z + v4.w * v4.w;
    }
    __shared__ float shs[32], shss[32];
    int lane = threadIdx.x & 31, wid = threadIdx.x >> 5;
#pragma unroll
    for (int o = 16; o > 0; o >>= 1) {
        s  += __shfl_down_sync(0xffffffffu, s, o);
        ss += __shfl_down_sync(0xffffffffu, ss, o);
    }
    if (lane == 0) { shs[wid] = s; shss[wid] = ss; }
    __syncthreads();
    if (wid == 0) {
        int nw = blockDim.x >> 5;
        s  = (lane < nw) ? shs[lane]  : 0.f;
        ss = (lane < nw) ? shss[lane] : 0.f;
#pragma unroll
        for (int o = 16; o > 0; o >>= 1) {
            s  += __shfl_down_sync(0xffffffffu, s, o);
            ss += __shfl_down_sync(0xffffffffu, ss, o);
        }
        if (lane == 0) {
            part[((size_t)c * gridDim.y + b) * 2 + 0] = s;
            part[((size_t)c * gridDim.y + b) * 2 + 1] = ss;
        }
    }
}

__global__ void stats_final_kernel(const float* __restrict__ part,
                                   float* __restrict__ ms, int nb, float invN)
{
    int c = blockIdx.x;
    float s = 0.f, ss = 0.f;
    for (int i = threadIdx.x; i < nb; i += 32) {
        s  += part[((size_t)c * nb + i) * 2 + 0];
        ss += part[((size_t)c * nb + i) * 2 + 1];
    }
#pragma unroll
    for (int o = 16; o > 0; o >>= 1) {
        s  += __shfl_down_sync(0xffffffffu, s, o);
        ss += __shfl_down_sync(0xffffffffu, ss, o);
    }
    if (threadIdx.x == 0) {
        float m   = s * invN;
        float var = ss * invN - m * m;
        ms[c * 2 + 0] = m;
        ms[c * 2 + 1] = rsqrtf(var + EPS);
    }
}

__global__ void bn_relu_kernel(float* __restrict__ y,
                               const float* __restrict__ ms,
                               const float* __restrict__ g,
                               const float* __restrict__ be,
                               int C, size_t total4)
{
    size_t i = (size_t)blockIdx.x * blockDim.x + threadIdx.x;
    if (i >= total4) return;
    size_t e0 = i * 4;
    int c = (int)((e0 >> 10) % C);
    float mean = ms[c * 2], inv = ms[c * 2 + 1];
    float sc = inv * g[c];
    float sh = be[c] - mean * sc;
    float4 v = *(float4*)&y[e0];
    v.x = fmaxf(fmaf(v.x, sc, sh), 0.f);
    v.y = fmaxf(fmaf(v.y, sc, sh), 0.f);
    v.z = fmaxf(fmaf(v.z, sc, sh), 0.f);
    v.w = fmaxf(fmaf(v.w, sc, sh), 0.f);
    *(float4*)&y[e0] = v;
}

// ---------------------------------------------------------------------------
// Row softmax, L=1024, 256 threads x 4.
// ---------------------------------------------------------------------------
__global__ void softmax_kernel(float* __restrict__ e)
{
    float* row = e + (size_t)blockIdx.x * L;
    int tid = threadIdx.x;
    float4 x = *(float4*)&row[tid * 4];
    float mx = fmaxf(fmaxf(x.x, x.y), fmaxf(x.z, x.w));
    __shared__ float shm[32];
    __shared__ float shsum[32];
    int lane = tid & 31, wid = tid >> 5;
#pragma unroll
    for (int o = 16; o > 0; o >>= 1)
        mx = fmaxf(mx, __shfl_xor_sync(0xffffffffu, mx, o));
    if (lane == 0) shm[wid] = mx;
    __syncthreads();
    mx = shm[0];
#pragma unroll
    for (int w = 1; w < 8; w++) mx = fmaxf(mx, shm[w]);

    x.x = __expf(x.x - mx); x.y = __expf(x.y - mx);
    x.z = __expf(x.z - mx); x.w = __expf(x.w - mx);
    float s = x.x + x.y + x.z + x.w;
#pragma unroll
    for (int o = 16; o > 0; o >>= 1)
        s += __shfl_xor_sync(0xffffffffu, s, o);
    if (lane == 0) shsum[wid] = s;
    __syncthreads();
    s = 0.f;
#pragma unroll
    for (int w = 0; w < 8; w++) s += shsum[w];
    float inv = 1.f / s;
    x.x *= inv; x.y *= inv; x.z *= inv; x.w *= inv;
    *(float4*)&row[tid * 4] = x;
}

// ---------------------------------------------------------------------------
// outconv (64 -> 8)
// ---------------------------------------------------------------------------
__global__ void outconv_kernel(const float* __restrict__ x2,
                               const float* __restrict__ wo,
                               const float* __restrict__ bo,
                               float* __restrict__ out)
{
    __shared__ float sw[CIN * FCH];
    __shared__ float sb[CIN];
    for (int i = threadIdx.x; i < CIN * FCH; i += 256) sw[i] = wo[i];
    if (threadIdx.x < CIN) sb[threadIdx.x] = bo[threadIdx.x];
    __syncthreads();

    int b = blockIdx.y;
    int l = blockIdx.x * 256 + threadIdx.x;
    float xv[FCH];
#pragma unroll
    for (int f = 0; f < FCH; f++) xv[f] = x2[((size_t)b * FCH + f) * L + l];

    float* ob = out + (size_t)b * CIN * L + l;
#pragma unroll
    for (int o = 0; o < CIN; o++) {
        float s = sb[o];
#pragma unroll
        for (int f = 0; f < FCH; f++) s = fmaf(sw[o * FCH + f], xv[f], s);
        ob[(size_t)o * L] = s;
    }
}

// ---------------------------------------------------------------------------
extern "C" void kernel_launch(void* const* d_in, const int* in_sizes, int n_in,
                              void* d_out, int out_size)
{
    const float* z     = (const float*)d_in[0];
    const float* w_pre = (const float*)d_in[1];
    const float* b_pre = (const float*)d_in[2];
    const float* w0    = (const float*)d_in[3];
    const float* b0    = (const float*)d_in[4];
    const float* g0    = (const float*)d_in[5];
    const float* be0   = (const float*)d_in[6];
    const float* wq    = (const float*)d_in[7];
    const float* bq    = (const float*)d_in[8];
    const float* wk    = (const float*)d_in[9];
    const float* bk    = (const float*)d_in[10];
    const float* wv    = (const float*)d_in[11];
    const float* bv    = (const float*)d_in[12];
    const float* gamma = (const float*)d_in[13];
    const float* w1    = (const float*)d_in[14];
    const float* b1    = (const float*)d_in[15];
    const float* g1    = (const float*)d_in[16];
    const float* be1   = (const float*)d_in[17];
    const float* w_out = (const float*)d_in[18];
    const float* b_out = (const float*)d_in[19];
    float* out = (float*)d_out;

    float *x1, *x0, *qk, *vb, *eb, *ao, *x2, *wqk, *bqk;
    float *p0, *ms0, *p1, *ms1;
    cudaGetSymbolAddress((void**)&x1,  g_x1);
    cudaGetSymbolAddress((void**)&x0,  g_x0);
    cudaGetSymbolAddress((void**)&qk,  g_qk);
    cudaGetSymbolAddress((void**)&vb,  g_v);
    cudaGetSymbolAddress((void**)&eb,  g_e);
    cudaGetSymbolAddress((void**)&ao,  g_ao);
    cudaGetSymbolAddress((void**)&x2,  g_x2);
    cudaGetSymbolAddress((void**)&wqk, g_wqk);
    cudaGetSymbolAddress((void**)&bqk, g_bqk);
    cudaGetSymbolAddress((void**)&p0,  g_part0);
    cudaGetSymbolAddress((void**)&ms0, g_ms0);
    cudaGetSymbolAddress((void**)&p1,  g_part1);
    cudaGetSymbolAddress((void**)&ms1, g_ms1);

    const float invN = 1.f / (float)(BATCH * L);
    constexpr int SMEM_BIG = 73728;   // 2*(4608+4608)*4
    constexpr int SMEM_64  = 55296;   // 2*(2304+4608)*4

    cudaFuncSetAttribute(gemm_tf32_kernel<0, 0, 1>,
                         cudaFuncAttributeMaxDynamicSharedMemorySize, SMEM_BIG);
    cudaFuncSetAttribute(gemm_tf32_kernel<1, 0, 0>,
                         cudaFuncAttributeMaxDynamicSharedMemorySize, SMEM_BIG);
    cudaFuncSetAttribute(gemm_tf32_kernel<0, 1, 3>,
                         cudaFuncAttributeMaxDynamicSharedMemorySize, SMEM_BIG);
    cudaFuncSetAttribute(gemm_tf32_64_kernel,
                         cudaFuncAttributeMaxDynamicSharedMemorySize, SMEM_64);

    // 0. pack wq||wk, bq||bk
    concat_qk_kernel<<<64, 256>>>(wq, wk, bq, bk, wqk, bqk);

    // 1. pre-linear (fp32 NT)
    gemm_kernel<64, 128, 16, 4, 8, 0, 1, 2><<<dim3(64, 1, 1), 256>>>(
        z, w_pre, x1, b_pre, 64, CIN * L, 128, 128, 128, CIN * L, 0, 0, 0);

    // 2. conv0 (8 -> 256)
    conv0_kernel<<<dim3(L / 256, BATCH), 256>>>(x1, w0, b0, x0);

    // 3. BN0 + relu
    stats_part_kernel<<<dim3(C0, BATCH), 256>>>(x0, p0, C0);
    stats_final_kernel<<<C0, 32>>>(p0, ms0, BATCH, invN);
    bn_relu_kernel<<<(BATCH * C0 * L / 4 + 255) / 256, 256>>>(
        x0, ms0, g0, be0, C0, (size_t)BATCH * C0 * L / 4);

    // 4a. packed q|k projection (tf32, BM=64)
    gemm_tf32_64_kernel<<<dim3(8, 1, BATCH), 256, SMEM_64>>>(
        wqk, x0, qk, bqk, C0, C0, L, L, 0, C0 * L, 2 * CQK * L);

    // 4b. v projection (tf32, BM=128)
    gemm_tf32_kernel<0, 0, 1><<<dim3(8, 2, BATCH), 256, SMEM_BIG>>>(
        wv, x0, vb, bv, nullptr, C0, C0, L, L, 0, C0 * L, C0 * L);

    // 5. energy (tf32): q = qk rows 0..31, k = qk rows 32..63
    gemm_tf32_kernel<1, 0, 0><<<dim3(8, 8, BATCH), 256, SMEM_BIG>>>(
        qk, qk + (size_t)CQK * L, eb, nullptr, nullptr, CQK, L, L, L,
        2 * CQK * L, 2 * CQK * L, (long long)L * L);

    // 6. softmax rows (in place)
    softmax_kernel<<<BATCH * L, 256>>>(eb);

    // 7+8. out GEMM fused residual (tf32): ao = gamma*(v@attn^T) + x0
    gemm_tf32_kernel<0, 1, 3><<<dim3(8, 2, BATCH), 256, SMEM_BIG>>>(
        vb, eb, ao, x0, gamma, L, L, L, L,
        C0 * L, (long long)L * L, C0 * L);

    // 9. conv1 (256 -> 64) (tf32, BM=64)
    gemm_tf32_64_kernel<<<dim3(8, 1, BATCH), 256, SMEM_64>>>(
        w1, ao, x2, b1, C0, C0, L, L, 0, C0 * L, FCH * L);

    // 10. BN1 + relu
    stats_part_kernel<<<dim3(FCH, BATCH), 256>>>(x2, p1, FCH);
    stats_final_kernel<<<FCH, 32>>>(p1, ms1, BATCH, invN);
    bn_relu_kernel<<<(BATCH * FCH * L / 4 + 255) / 256, 256>>>(
        x2, ms1, g1, be1, FCH, (size_t)BATCH * FCH * L / 4);

    // 11. output conv (64 -> 8)
    outconv_kernel<<<dim3(L / 256, BATCH), 256>>>(x2, w_out, b_out, out);
}